// round 14
// baseline (speedup 1.0000x reference)
#include <cuda_runtime.h>
#include <cuda_fp16.h>
#include <cstdint>

#define M_TOTAL   131072
#define NCODES    1024
#define DIM       128
#define MARGIN    1e-3f

// ---------------- device scratch (no allocs allowed) ----------------
__device__ float g_cnorm[NCODES];                         // ||c_n||^2
__device__ __align__(16) float  g_cbT [NCODES * DIM];     // codebook^T fp32 [n][k]
__device__ __align__(16) __half g_cbTh[NCODES * DIM];     // codebook^T fp16 [n][k]
__device__ int g_flag_rows[M_TOTAL];
__device__ int g_flag_count;

// ---------------- small prep kernels ----------------
__global__ void vq_reset() { g_flag_count = 0; }

__global__ void vq_prep_transpose(const float* __restrict__ cb) {
    int e = blockIdx.x * blockDim.x + threadIdx.x;   // e = k*1024 + n
    if (e < NCODES * DIM) {
        int k = e >> 10, n = e & (NCODES - 1);
        float v = cb[e];
        g_cbT [n * DIM + k] = v;
        g_cbTh[n * DIM + k] = __float2half_rn(v);
    }
}

__global__ void vq_prep_norm(const float* __restrict__ cb) {
    int n = blockIdx.x * blockDim.x + threadIdx.x;
    if (n < NCODES) {
        float s = 0.f;
        #pragma unroll 8
        for (int k = 0; k < DIM; k++) { float v = cb[k * NCODES + n]; s = fmaf(v, v, s); }
        g_cnorm[n] = s;
    }
}

// ---------------- helpers ----------------
__device__ __forceinline__ void mma16816(float* c, const unsigned* a, unsigned b0, unsigned b1) {
    asm volatile(
        "mma.sync.aligned.m16n8k16.row.col.f32.f16.f16.f32 "
        "{%0,%1,%2,%3}, {%4,%5,%6,%7}, {%8,%9}, {%0,%1,%2,%3};\n"
        : "+f"(c[0]), "+f"(c[1]), "+f"(c[2]), "+f"(c[3])
        : "r"(a[0]), "r"(a[1]), "r"(a[2]), "r"(a[3]), "r"(b0), "r"(b1));
}

__device__ __forceinline__ void merge_scalar(float v, int n, float& best, int& bidx, float& sec) {
    if (v > best) { sec = best; best = v; bidx = n; }
    else          { sec = fmaxf(sec, v); }
}

// merge two (best, idx, second) triples; equal values from distinct codes force sec=best (-> flagged)
__device__ __forceinline__ void merge_pair(float& best, int& bidx, float& sec,
                                           float b2, int i2, float s2) {
    if (b2 > best)      { sec = fmaxf(s2, best); best = b2; bidx = i2; }
    else if (b2 < best) { sec = fmaxf(sec, b2); }
    else                { sec = best; bidx = min(bidx, i2); }
}

// ---------------- main fused GEMM + argmax + gather ----------------
// grid 1024 (128 rows each), 256 threads (8 warps x 16 rows)
#define SM_AS   0                       // 128 rows x stride 136 halves  = 34816 B
#define SM_BS   34816                   // 256 rows x stride 136 halves  = 69632 B
#define SM_HS   (34816 + 69632)         // 1024 f32                      =  4096 B
#define SM_RIDX (34816 + 69632 + 4096)  // 128 int                       =   512 B
#define SMEM_MAIN (34816 + 69632 + 4096 + 512)

__global__ void __launch_bounds__(256) vq_main(const float* __restrict__ x,
                                               float* __restrict__ out) {
    extern __shared__ char smem[];
    __half* as  = (__half*)(smem + SM_AS);
    __half* bs  = (__half*)(smem + SM_BS);
    float*  hs  = (float*) (smem + SM_HS);
    int*    ridx= (int*)   (smem + SM_RIDX);

    const int tid  = threadIdx.x;
    const int w    = tid >> 5;
    const int lane = tid & 31;
    const int g    = lane >> 2;     // groupID
    const int t4   = lane & 3;      // thread-in-group
    const int m0   = blockIdx.x * 128;

    // --- load x tile [128][128] fp32 -> fp16 smem (padded stride 136) ---
    #pragma unroll
    for (int i = 0; i < 16; i++) {
        int idx = tid + i * 256;          // 4096 float4 slots
        int r = idx >> 5, c4 = idx & 31;
        float4 v = *(const float4*)(x + (size_t)(m0 + r) * DIM + c4 * 4);
        __half2 h0 = __floats2half2_rn(v.x, v.y);
        __half2 h1 = __floats2half2_rn(v.z, v.w);
        *(__half2*)(as + r * 136 + c4 * 4)     = h0;
        *(__half2*)(as + r * 136 + c4 * 4 + 2) = h1;
    }
    for (int i = tid; i < NCODES; i += 256) hs[i] = 0.5f * g_cnorm[i];
    __syncthreads();

    // --- A fragments for this warp's 16 rows, all K in registers ---
    unsigned afr[8][4];
    const int rowA = (w << 4) + g;
    #pragma unroll
    for (int ks = 0; ks < 8; ks++) {
        int cb0 = t4 * 2 + ks * 16;
        afr[ks][0] = *(const unsigned*)(as + rowA       * 136 + cb0);
        afr[ks][1] = *(const unsigned*)(as + (rowA + 8) * 136 + cb0);
        afr[ks][2] = *(const unsigned*)(as + rowA       * 136 + cb0 + 8);
        afr[ks][3] = *(const unsigned*)(as + (rowA + 8) * 136 + cb0 + 8);
    }

    float bestA = -3.4e38f, secA = -3.4e38f; int idxA = 0;   // row rowA
    float bestB = -3.4e38f, secB = -3.4e38f; int idxB = 0;   // row rowA + 8

    for (int ch = 0; ch < 4; ch++) {
        // --- stage 256 codebook rows (fp16 [n][k]) into smem ---
        #pragma unroll
        for (int i = 0; i < 16; i++) {
            int idx = tid + i * 256;        // 4096 uint4 slots
            int n = idx >> 4, seg = idx & 15;
            uint4 v = *(const uint4*)(g_cbTh + (size_t)(ch * 256 + n) * DIM + seg * 8);
            *(uint4*)(bs + n * 136 + seg * 8) = v;
        }
        __syncthreads();

        for (int grp = 0; grp < 8; grp++) {     // 32 codes per group
            float acc[16];
            #pragma unroll
            for (int q = 0; q < 16; q++) acc[q] = 0.f;
            #pragma unroll
            for (int ks = 0; ks < 8; ks++) {
                #pragma unroll
                for (int tl = 0; tl < 4; tl++) {
                    int nloc = grp * 32 + tl * 8 + g;
                    unsigned b0 = *(const unsigned*)(bs + nloc * 136 + t4 * 2 + ks * 16);
                    unsigned b1 = *(const unsigned*)(bs + nloc * 136 + t4 * 2 + ks * 16 + 8);
                    mma16816(&acc[tl * 4], afr[ks], b0, b1);
                }
            }
            #pragma unroll
            for (int tl = 0; tl < 4; tl++) {
                int n = ch * 256 + grp * 32 + tl * 8 + t4 * 2;
                float h0 = hs[n], h1 = hs[n + 1];
                merge_scalar(acc[tl*4+0] - h0, n,     bestA, idxA, secA);
                merge_scalar(acc[tl*4+1] - h1, n + 1, bestA, idxA, secA);
                merge_scalar(acc[tl*4+2] - h0, n,     bestB, idxB, secB);
                merge_scalar(acc[tl*4+3] - h1, n + 1, bestB, idxB, secB);
            }
        }
        __syncthreads();
    }

    // --- reduce across the 4 lanes of each row group ---
    #pragma unroll
    for (int off = 1; off < 4; off <<= 1) {
        float b2 = __shfl_xor_sync(0xFFFFFFFFu, bestA, off);
        float s2 = __shfl_xor_sync(0xFFFFFFFFu, secA,  off);
        int   i2 = __shfl_xor_sync(0xFFFFFFFFu, idxA,  off);
        merge_pair(bestA, idxA, secA, b2, i2, s2);
        b2 = __shfl_xor_sync(0xFFFFFFFFu, bestB, off);
        s2 = __shfl_xor_sync(0xFFFFFFFFu, secB,  off);
        i2 = __shfl_xor_sync(0xFFFFFFFFu, idxB,  off);
        merge_pair(bestB, idxB, secB, b2, i2, s2);
    }

    if (t4 == 0) {
        int rl = (w << 4) + g;
        ridx[rl]     = idxA;
        ridx[rl + 8] = idxB;
        if (bestA - secA < MARGIN) { int p = atomicAdd(&g_flag_count, 1); g_flag_rows[p] = m0 + rl; }
        if (bestB - secB < MARGIN) { int p = atomicAdd(&g_flag_count, 1); g_flag_rows[p] = m0 + rl + 8; }
    }
    __syncthreads();

    // --- gather: out = x + (q - x), fp32, coalesced ---
    #pragma unroll 4
    for (int i = 0; i < 64; i++) {
        int e = tid + i * 256;              // 16384 elements
        int rl = e >> 7, k = e & 127;
        int n = ridx[rl];
        float xv = x[(size_t)(m0 + rl) * DIM + k];
        float qv = g_cbT[n * DIM + k];
        out[(size_t)(m0 + rl) * DIM + k] = xv + (qv - xv);
    }
}

// ---------------- exact fp32 rescore of margin-flagged rows ----------------
#define RS_XS   0                        // 32*128 f32  = 16384
#define RS_CS   16384                    // 128 x stride 132 f32 = 67584
#define RS_XX   (16384 + 67584)          // 32 f32
#define RS_BK   (RS_XX + 128)            // 32 u64
#define RS_ROWS (RS_BK + 256)            // 32 int
#define SMEM_RESCORE (RS_ROWS + 128)

__global__ void __launch_bounds__(256) vq_rescore(const float* __restrict__ x,
                                                  const float* __restrict__ cb,
                                                  float* __restrict__ out) {
    extern __shared__ char smem[];
    float* xs = (float*)(smem + RS_XS);
    float* cs = (float*)(smem + RS_CS);
    float* xx = (float*)(smem + RS_XX);
    unsigned long long* bkey = (unsigned long long*)(smem + RS_BK);
    int* rows = (int*)(smem + RS_ROWS);

    const int tid = threadIdx.x;
    const int nf = g_flag_count;

    for (int base = blockIdx.x * 32; base < nf; base += gridDim.x * 32) {
        int cnt = min(32, nf - base);
        if (tid < 32) {
            rows[tid] = g_flag_rows[base + min(tid, cnt - 1)];
            bkey[tid] = 0xFFFFFFFFFFFFFFFFull;
        }
        __syncthreads();
        #pragma unroll
        for (int i = 0; i < 16; i++) {
            int idx = tid + i * 256; int r = idx >> 7, k = idx & 127;
            xs[r * 128 + k] = x[(size_t)rows[r] * DIM + k];
        }
        __syncthreads();
        if (tid < 32) {
            float s = 0.f;
            for (int k = 0; k < DIM; k++) { float v = xs[tid * 128 + k]; s = fmaf(v, v, s); }
            xx[tid] = s;
        }
        __syncthreads();

        const int rp = tid >> 4;         // 0..15 -> rows 2rp, 2rp+1
        const int cg = tid & 15;         // columns cg + 16*j, j=0..7
        const int r0 = rp * 2, r1 = r0 + 1;

        for (int chn = 0; chn < 8; chn++) {       // 128 codes per chunk
            #pragma unroll
            for (int i = 0; i < 16; i++) {
                int idx = tid + i * 256;           // 4096 float4
                int k = idx >> 5, j4 = idx & 31;
                float4 v = *(const float4*)(cb + (size_t)k * NCODES + chn * 128 + j4 * 4);
                *(float4*)(cs + k * 132 + j4 * 4) = v;
            }
            __syncthreads();

            float acc0[8], acc1[8];
            #pragma unroll
            for (int j = 0; j < 8; j++) { acc0[j] = 0.f; acc1[j] = 0.f; }
            for (int k = 0; k < DIM; k++) {
                float x0 = xs[r0 * 128 + k], x1 = xs[r1 * 128 + k];
                #pragma unroll
                for (int j = 0; j < 8; j++) {
                    float cv = cs[k * 132 + cg + 16 * j];
                    acc0[j] = fmaf(x0, cv, acc0[j]);
                    acc1[j] = fmaf(x1, cv, acc1[j]);
                }
            }
            unsigned long long k0 = 0xFFFFFFFFFFFFFFFFull, k1 = k0;
            #pragma unroll
            for (int j = 0; j < 8; j++) {
                int n = chn * 128 + cg + 16 * j;
                float d0 = (xx[r0] + g_cnorm[n]) - 2.0f * acc0[j];
                float d1 = (xx[r1] + g_cnorm[n]) - 2.0f * acc1[j];
                unsigned long long e0 = ((unsigned long long)__float_as_uint(d0) << 32) | (unsigned)n;
                unsigned long long e1 = ((unsigned long long)__float_as_uint(d1) << 32) | (unsigned)n;
                k0 = min(k0, e0); k1 = min(k1, e1);
            }
            if (r0 < cnt) atomicMin(&bkey[r0], k0);
            if (r1 < cnt) atomicMin(&bkey[r1], k1);
            __syncthreads();
        }

        #pragma unroll
        for (int i = 0; i < 16; i++) {
            int idx = tid + i * 256; int r = idx >> 7, k = idx & 127;
            if (r < cnt) {
                int n = (int)(bkey[r] & 0xFFFFFFFFull);
                float xv = xs[r * 128 + k];
                float qv = g_cbT[n * DIM + k];
                out[(size_t)rows[r] * DIM + k] = xv + (qv - xv);
            }
        }
        __syncthreads();
    }
}

// ---------------- launch ----------------
extern "C" void kernel_launch(void* const* d_in, const int* in_sizes, int n_in,
                              void* d_out, int out_size) {
    const float* x  = (const float*)d_in[0];   // [131072,128] fp32
    const float* cb = (const float*)d_in[1];   // [128,1024]  fp32
    float* out = (float*)d_out;

    cudaFuncSetAttribute(vq_main,    cudaFuncAttributeMaxDynamicSharedMemorySize, SMEM_MAIN);
    cudaFuncSetAttribute(vq_rescore, cudaFuncAttributeMaxDynamicSharedMemorySize, SMEM_RESCORE);

    vq_reset<<<1, 32>>>();
    vq_prep_transpose<<<(NCODES * DIM + 255) / 256, 256>>>(cb);
    vq_prep_norm<<<(NCODES + 255) / 256, 256>>>(cb);
    vq_main<<<M_TOTAL / 128, 256, SMEM_MAIN>>>(x, out);
    vq_rescore<<<256, 256, SMEM_RESCORE>>>(x, cb, out);
}

// round 15
// speedup vs baseline: 1.0057x; 1.0057x over previous
#include <cuda_runtime.h>
#include <cuda_fp16.h>
#include <cstdint>

#define M_TOTAL   131072
#define NCODES    1024
#define DIM       128
#define MARGIN    1e-3f

// ---------------- device scratch (no allocs allowed) ----------------
__device__ float g_cnorm[NCODES];                         // ||c_n||^2
__device__ __align__(16) float  g_cbT [NCODES * DIM];     // codebook^T fp32 [n][k]
__device__ __align__(16) __half g_cbTh[NCODES * DIM];     // codebook^T fp16 [n][k]
__device__ int g_flag_rows[M_TOTAL];
__device__ int g_flag_count;

// ---------------- small prep kernels ----------------
__global__ void vq_reset() { g_flag_count = 0; }

__global__ void vq_prep_transpose(const float* __restrict__ cb) {
    int e = blockIdx.x * blockDim.x + threadIdx.x;   // e = k*1024 + n
    if (e < NCODES * DIM) {
        int k = e >> 10, n = e & (NCODES - 1);
        float v = cb[e];
        g_cbT [n * DIM + k] = v;
        g_cbTh[n * DIM + k] = __float2half_rn(v);
    }
}

__global__ void vq_prep_norm(const float* __restrict__ cb) {
    int n = blockIdx.x * blockDim.x + threadIdx.x;
    if (n < NCODES) {
        float s = 0.f;
        #pragma unroll 8
        for (int k = 0; k < DIM; k++) { float v = cb[k * NCODES + n]; s = fmaf(v, v, s); }
        g_cnorm[n] = s;
    }
}

// ---------------- helpers ----------------
__device__ __forceinline__ void mma16816(float* c, const unsigned* a, unsigned b0, unsigned b1) {
    asm volatile(
        "mma.sync.aligned.m16n8k16.row.col.f32.f16.f16.f32 "
        "{%0,%1,%2,%3}, {%4,%5,%6,%7}, {%8,%9}, {%0,%1,%2,%3};\n"
        : "+f"(c[0]), "+f"(c[1]), "+f"(c[2]), "+f"(c[3])
        : "r"(a[0]), "r"(a[1]), "r"(a[2]), "r"(a[3]), "r"(b0), "r"(b1));
}

__device__ __forceinline__ void merge_scalar(float v, int n, float& best, int& bidx, float& sec) {
    if (v > best) { sec = best; best = v; bidx = n; }
    else          { sec = fmaxf(sec, v); }
}

// merge two (best, idx, second) triples; equal values from distinct codes force sec=best (-> flagged)
__device__ __forceinline__ void merge_pair(float& best, int& bidx, float& sec,
                                           float b2, int i2, float s2) {
    if (b2 > best)      { sec = fmaxf(s2, best); best = b2; bidx = i2; }
    else if (b2 < best) { sec = fmaxf(sec, b2); }
    else                { sec = best; bidx = min(bidx, i2); }
}

// ---------------- main fused GEMM + argmax + gather ----------------
// grid 1024 (128 rows each), 256 threads (8 warps x 16 rows)
#define SM_AS   0                       // 128 rows x stride 136 halves  = 34816 B
#define SM_BS   34816                   // 256 rows x stride 136 halves  = 69632 B
#define SM_HS   (34816 + 69632)         // 1024 f32                      =  4096 B
#define SM_RIDX (34816 + 69632 + 4096)  // 128 int                       =   512 B
#define SMEM_MAIN (34816 + 69632 + 4096 + 512)

__global__ void __launch_bounds__(256) vq_main(const float* __restrict__ x,
                                               float* __restrict__ out) {
    extern __shared__ char smem[];
    __half* as  = (__half*)(smem + SM_AS);
    __half* bs  = (__half*)(smem + SM_BS);
    float*  hs  = (float*) (smem + SM_HS);
    int*    ridx= (int*)   (smem + SM_RIDX);

    const int tid  = threadIdx.x;
    const int w    = tid >> 5;
    const int lane = tid & 31;
    const int g    = lane >> 2;     // groupID
    const int t4   = lane & 3;      // thread-in-group
    const int m0   = blockIdx.x * 128;

    // --- load x tile [128][128] fp32 -> fp16 smem (padded stride 136) ---
    #pragma unroll
    for (int i = 0; i < 16; i++) {
        int idx = tid + i * 256;          // 4096 float4 slots
        int r = idx >> 5, c4 = idx & 31;
        float4 v = *(const float4*)(x + (size_t)(m0 + r) * DIM + c4 * 4);
        __half2 h0 = __floats2half2_rn(v.x, v.y);
        __half2 h1 = __floats2half2_rn(v.z, v.w);
        *(__half2*)(as + r * 136 + c4 * 4)     = h0;
        *(__half2*)(as + r * 136 + c4 * 4 + 2) = h1;
    }
    for (int i = tid; i < NCODES; i += 256) hs[i] = 0.5f * g_cnorm[i];
    __syncthreads();

    // --- A fragments for this warp's 16 rows, all K in registers ---
    unsigned afr[8][4];
    const int rowA = (w << 4) + g;
    #pragma unroll
    for (int ks = 0; ks < 8; ks++) {
        int cb0 = t4 * 2 + ks * 16;
        afr[ks][0] = *(const unsigned*)(as + rowA       * 136 + cb0);
        afr[ks][1] = *(const unsigned*)(as + (rowA + 8) * 136 + cb0);
        afr[ks][2] = *(const unsigned*)(as + rowA       * 136 + cb0 + 8);
        afr[ks][3] = *(const unsigned*)(as + (rowA + 8) * 136 + cb0 + 8);
    }

    float bestA = -3.4e38f, secA = -3.4e38f; int idxA = 0;   // row rowA
    float bestB = -3.4e38f, secB = -3.4e38f; int idxB = 0;   // row rowA + 8

    for (int ch = 0; ch < 4; ch++) {
        // --- stage 256 codebook rows (fp16 [n][k]) into smem ---
        #pragma unroll
        for (int i = 0; i < 16; i++) {
            int idx = tid + i * 256;        // 4096 uint4 slots
            int n = idx >> 4, seg = idx & 15;
            uint4 v = *(const uint4*)(g_cbTh + (size_t)(ch * 256 + n) * DIM + seg * 8);
            *(uint4*)(bs + n * 136 + seg * 8) = v;
        }
        __syncthreads();

        for (int grp = 0; grp < 8; grp++) {     // 32 codes per group
            float acc[16];
            #pragma unroll
            for (int q = 0; q < 16; q++) acc[q] = 0.f;
            #pragma unroll
            for (int ks = 0; ks < 8; ks++) {
                #pragma unroll
                for (int tl = 0; tl < 4; tl++) {
                    int nloc = grp * 32 + tl * 8 + g;
                    unsigned b0 = *(const unsigned*)(bs + nloc * 136 + t4 * 2 + ks * 16);
                    unsigned b1 = *(const unsigned*)(bs + nloc * 136 + t4 * 2 + ks * 16 + 8);
                    mma16816(&acc[tl * 4], afr[ks], b0, b1);
                }
            }
            #pragma unroll
            for (int tl = 0; tl < 4; tl++) {
                int n = ch * 256 + grp * 32 + tl * 8 + t4 * 2;
                float h0 = hs[n], h1 = hs[n + 1];
                merge_scalar(acc[tl*4+0] - h0, n,     bestA, idxA, secA);
                merge_scalar(acc[tl*4+1] - h1, n + 1, bestA, idxA, secA);
                merge_scalar(acc[tl*4+2] - h0, n,     bestB, idxB, secB);
                merge_scalar(acc[tl*4+3] - h1, n + 1, bestB, idxB, secB);
            }
        }
        __syncthreads();
    }

    // --- reduce across the 4 lanes of each row group ---
    #pragma unroll
    for (int off = 1; off < 4; off <<= 1) {
        float b2 = __shfl_xor_sync(0xFFFFFFFFu, bestA, off);
        float s2 = __shfl_xor_sync(0xFFFFFFFFu, secA,  off);
        int   i2 = __shfl_xor_sync(0xFFFFFFFFu, idxA,  off);
        merge_pair(bestA, idxA, secA, b2, i2, s2);
        b2 = __shfl_xor_sync(0xFFFFFFFFu, bestB, off);
        s2 = __shfl_xor_sync(0xFFFFFFFFu, secB,  off);
        i2 = __shfl_xor_sync(0xFFFFFFFFu, idxB,  off);
        merge_pair(bestB, idxB, secB, b2, i2, s2);
    }

    if (t4 == 0) {
        int rl = (w << 4) + g;
        ridx[rl]     = idxA;
        ridx[rl + 8] = idxB;
        if (bestA - secA < MARGIN) { int p = atomicAdd(&g_flag_count, 1); g_flag_rows[p] = m0 + rl; }
        if (bestB - secB < MARGIN) { int p = atomicAdd(&g_flag_count, 1); g_flag_rows[p] = m0 + rl + 8; }
    }
    __syncthreads();

    // --- gather: out = x + (q - x), fp32, coalesced ---
    #pragma unroll 4
    for (int i = 0; i < 64; i++) {
        int e = tid + i * 256;              // 16384 elements
        int rl = e >> 7, k = e & 127;
        int n = ridx[rl];
        float xv = x[(size_t)(m0 + rl) * DIM + k];
        float qv = g_cbT[n * DIM + k];
        out[(size_t)(m0 + rl) * DIM + k] = xv + (qv - xv);
    }
}

// ---------------- exact fp32 rescore of margin-flagged rows ----------------
#define RS_XS   0                        // 32*128 f32  = 16384
#define RS_CS   16384                    // 128 x stride 132 f32 = 67584
#define RS_XX   (16384 + 67584)          // 32 f32
#define RS_BK   (RS_XX + 128)            // 32 u64
#define RS_ROWS (RS_BK + 256)            // 32 int
#define SMEM_RESCORE (RS_ROWS + 128)

__global__ void __launch_bounds__(256) vq_rescore(const float* __restrict__ x,
                                                  const float* __restrict__ cb,
                                                  float* __restrict__ out) {
    extern __shared__ char smem[];
    float* xs = (float*)(smem + RS_XS);
    float* cs = (float*)(smem + RS_CS);
    float* xx = (float*)(smem + RS_XX);
    unsigned long long* bkey = (unsigned long long*)(smem + RS_BK);
    int* rows = (int*)(smem + RS_ROWS);

    const int tid = threadIdx.x;
    const int nf = g_flag_count;

    for (int base = blockIdx.x * 32; base < nf; base += gridDim.x * 32) {
        int cnt = min(32, nf - base);
        if (tid < 32) {
            rows[tid] = g_flag_rows[base + min(tid, cnt - 1)];
            bkey[tid] = 0xFFFFFFFFFFFFFFFFull;
        }
        __syncthreads();
        #pragma unroll
        for (int i = 0; i < 16; i++) {
            int idx = tid + i * 256; int r = idx >> 7, k = idx & 127;
            xs[r * 128 + k] = x[(size_t)rows[r] * DIM + k];
        }
        __syncthreads();
        if (tid < 32) {
            float s = 0.f;
            for (int k = 0; k < DIM; k++) { float v = xs[tid * 128 + k]; s = fmaf(v, v, s); }
            xx[tid] = s;
        }
        __syncthreads();

        const int rp = tid >> 4;         // 0..15 -> rows 2rp, 2rp+1
        const int cg = tid & 15;         // columns cg + 16*j, j=0..7
        const int r0 = rp * 2, r1 = r0 + 1;

        for (int chn = 0; chn < 8; chn++) {       // 128 codes per chunk
            #pragma unroll
            for (int i = 0; i < 16; i++) {
                int idx = tid + i * 256;           // 4096 float4
                int k = idx >> 5, j4 = idx & 31;
                float4 v = *(const float4*)(cb + (size_t)k * NCODES + chn * 128 + j4 * 4);
                *(float4*)(cs + k * 132 + j4 * 4) = v;
            }
            __syncthreads();

            float acc0[8], acc1[8];
            #pragma unroll
            for (int j = 0; j < 8; j++) { acc0[j] = 0.f; acc1[j] = 0.f; }
            for (int k = 0; k < DIM; k++) {
                float x0 = xs[r0 * 128 + k], x1 = xs[r1 * 128 + k];
                #pragma unroll
                for (int j = 0; j < 8; j++) {
                    float cv = cs[k * 132 + cg + 16 * j];
                    acc0[j] = fmaf(x0, cv, acc0[j]);
                    acc1[j] = fmaf(x1, cv, acc1[j]);
                }
            }
            unsigned long long k0 = 0xFFFFFFFFFFFFFFFFull, k1 = k0;
            #pragma unroll
            for (int j = 0; j < 8; j++) {
                int n = chn * 128 + cg + 16 * j;
                float d0 = (xx[r0] + g_cnorm[n]) - 2.0f * acc0[j];
                float d1 = (xx[r1] + g_cnorm[n]) - 2.0f * acc1[j];
                unsigned long long e0 = ((unsigned long long)__float_as_uint(d0) << 32) | (unsigned)n;
                unsigned long long e1 = ((unsigned long long)__float_as_uint(d1) << 32) | (unsigned)n;
                k0 = min(k0, e0); k1 = min(k1, e1);
            }
            if (r0 < cnt) atomicMin(&bkey[r0], k0);
            if (r1 < cnt) atomicMin(&bkey[r1], k1);
            __syncthreads();
        }

        #pragma unroll
        for (int i = 0; i < 16; i++) {
            int idx = tid + i * 256; int r = idx >> 7, k = idx & 127;
            if (r < cnt) {
                int n = (int)(bkey[r] & 0xFFFFFFFFull);
                float xv = xs[r * 128 + k];
                float qv = g_cbT[n * DIM + k];
                out[(size_t)rows[r] * DIM + k] = xv + (qv - xv);
            }
        }
        __syncthreads();
    }
}

// ---------------- launch ----------------
extern "C" void kernel_launch(void* const* d_in, const int* in_sizes, int n_in,
                              void* d_out, int out_size) {
    const float* x  = (const float*)d_in[0];   // [131072,128] fp32
    const float* cb = (const float*)d_in[1];   // [128,1024]  fp32
    float* out = (float*)d_out;

    cudaFuncSetAttribute(vq_main,    cudaFuncAttributeMaxDynamicSharedMemorySize, SMEM_MAIN);
    cudaFuncSetAttribute(vq_rescore, cudaFuncAttributeMaxDynamicSharedMemorySize, SMEM_RESCORE);

    vq_reset<<<1, 32>>>();
    vq_prep_transpose<<<(NCODES * DIM + 255) / 256, 256>>>(cb);
    vq_prep_norm<<<(NCODES + 255) / 256, 256>>>(cb);
    vq_main<<<M_TOTAL / 128, 256, SMEM_MAIN>>>(x, out);
    vq_rescore<<<256, 256, SMEM_RESCORE>>>(x, cb, out);
}